// round 8
// baseline (speedup 1.0000x reference)
#include <cuda_runtime.h>
#include <cuda_bf16.h>
#include <cstdint>

#define CIN   256
#define COUT  256
#define LEN   8192
#define KK    7
#define BATCH 4
#define NT    128    // l-tile of main kernel
#define TLO   128    // l-tile of offsets kernel
#define NCHUNK 4     // i-chunks of 64 per k

// ---------------- device scratch ----------------
__device__ int2          g_tidx[BATCH * KK * LEN];   // (x0c, x1c)
__device__ float2        g_tw[BATCH * KK * LEN];     // (wa, wb)
// weight tiles: t = ((k*4+ic)*2+oh)*2+plane, each [128 o][64 i] bf16, SW128 pre-swizzled
__device__ __nv_bfloat16 g_wA[KK * NCHUNK * 2 * 2 * 8192];

#define SWZ128(x)  ((x) ^ (((x) >> 3) & 0x70))
#define SLOT_BYTES 65536

// ---------------- PTX helpers (portable, sm_80-era) ----------------
__device__ __forceinline__ uint32_t smem_u32(const void* p) {
    uint32_t a;
    asm("{ .reg .u64 t; cvta.to.shared.u64 t, %1; cvt.u32.u64 %0, t; }" : "=r"(a) : "l"(p));
    return a;
}
__device__ __forceinline__ void cp16(uint32_t dst, const void* src) {
    asm volatile("cp.async.cg.shared.global [%0], [%1], 16;" :: "r"(dst), "l"(src));
}
__device__ __forceinline__ void ldsm4(uint32_t* r, uint32_t addr) {
    asm volatile("ldmatrix.sync.aligned.m8n8.x4.shared.b16 {%0,%1,%2,%3}, [%4];"
        : "=r"(r[0]), "=r"(r[1]), "=r"(r[2]), "=r"(r[3]) : "r"(addr));
}
__device__ __forceinline__ void mma16816(float* c, const uint32_t* a, const uint32_t* b) {
    asm volatile("mma.sync.aligned.m16n8k16.row.col.f32.bf16.bf16.f32 "
        "{%0,%1,%2,%3}, {%4,%5,%6,%7}, {%8,%9}, {%0,%1,%2,%3};"
        : "+f"(c[0]), "+f"(c[1]), "+f"(c[2]), "+f"(c[3])
        : "r"(a[0]), "r"(a[1]), "r"(a[2]), "r"(a[3]), "r"(b[0]), "r"(b[1]));
}
// pack two f32 -> bf16x2 (rn), and expose the rounded hi-plane floats via bit ops
__device__ __forceinline__ uint32_t cvt_bf16x2(float lo, float hi) {
    uint32_t r;
    asm("cvt.rn.bf16x2.f32 %0, %1, %2;" : "=r"(r) : "f"(hi), "f"(lo));
    return r;
}
#define BAR_SYNC(id)   asm volatile("bar.sync %0, %1;"   :: "r"(id), "r"(384) : "memory")
#define BAR_ARRIVE(id) asm volatile("bar.arrive %0, %1;" :: "r"(id), "r"(384) : "memory")

// ---------- kernel 1: weight split + pre-swizzle ----------
__global__ void wprep_kernel(const float* __restrict__ w) {
    int e = blockIdx.x * 256 + threadIdx.x;
    if (e >= KK * NCHUNK * 2 * 2 * 8192) return;
    int t  = e >> 13;
    int r  = e & 8191;
    int o  = r >> 6;
    int i  = r & 63;
    int plane = t & 1;
    int oh    = (t >> 1) & 1;
    int ic    = (t >> 2) & 3;
    int k     = t >> 4;
    float v = w[((oh * 128 + o) * CIN + ic * 64 + i) * KK + k];
    __nv_bfloat16 hi  = __float2bfloat16(v);
    __nv_bfloat16 val = plane ? __float2bfloat16(v - __bfloat162float(hi)) : hi;
    uint32_t swz = SWZ128((uint32_t)(o * 128 + i * 2));
    g_wA[t * 8192 + (swz >> 1)] = val;
}

// ---------- kernel 2: offset conv + interpolation tables ----------
__global__ __launch_bounds__(256, 1) void offsets_kernel(
    const float* __restrict__ x,
    const float* __restrict__ ow,
    const float* __restrict__ ob)
{
    extern __shared__ float sm[];
    float* xs  = sm;              // 256 * 136
    float* ows = sm + 256 * 136;  // 7 * 256 * 8

    int tid = threadIdx.x;
    int b   = blockIdx.y;
    int l0  = blockIdx.x * TLO;
    const float* xb = x + (size_t)b * CIN * LEN;

    for (int idx = tid; idx < 256 * 134; idx += 256) {
        int i = idx / 134;
        int c = idx - i * 134;
        int g = l0 - 3 + c;
        xs[i * 136 + c] = (g >= 0 && g < LEN) ? xb[i * LEN + g] : 0.0f;
    }
    for (int e = tid; e < KK * CIN * KK; e += 256) {
        int r  = e / 7;
        int kk = e - r * 7;
        ows[r * 8 + kk] = ow[e];
    }
    __syncthreads();

    int w    = tid >> 5;
    int lane = tid & 31;
    if (w < 7) {
        int k = w;
        float a0 = 0.f, a1 = 0.f, a2 = 0.f, a3 = 0.f;
        const float* xrow0 = xs + 4 * lane;
        const float* wrow  = ows + k * 256 * 8;
        #pragma unroll 4
        for (int i = 0; i < 256; i++) {
            const float4* xr = (const float4*)(xrow0 + i * 136);
            float4 A = xr[0], B4 = xr[1], C4 = xr[2];
            float xw[12] = {A.x, A.y, A.z, A.w, B4.x, B4.y, B4.z, B4.w,
                            C4.x, C4.y, C4.z, C4.w};
            const float4* wr = (const float4*)(wrow + i * 8);
            float4 W0 = wr[0], W1 = wr[1];
            float wv[7] = {W0.x, W0.y, W0.z, W0.w, W1.x, W1.y, W1.z};
            #pragma unroll
            for (int kk = 0; kk < 7; kk++) {
                a0 += wv[kk] * xw[0 + kk];
                a1 += wv[kk] * xw[1 + kk];
                a2 += wv[kk] * xw[2 + kk];
                a3 += wv[kk] * xw[3 + kk];
            }
        }
        float bk = ob[k];
        float accs[4] = {a0, a1, a2, a3};
        #pragma unroll
        for (int d = 0; d < 4; d++) {
            int lg = l0 + 4 * lane + d;
            float loc = (float)(lg + k) + accs[d] + bk;
            int ix0 = (int)floorf(loc);
            int i0c = min(max(ix0, 0), LEN - 1);
            int i1c = min(max(ix0 + 1, 0), LEN - 1);
            int o = (b * 7 + k) * LEN + lg;
            g_tidx[o] = make_int2(i0c, i1c);
            g_tw[o]   = make_float2((float)i1c - loc, loc - (float)i0c);
        }
    }
}

// ---------- kernel 3: warp-specialized GEMM (bf16 split x3) ----------
// 384 threads: warps 0-7 consumers (mma), warps 8-11 producers (A cp.async + B gather).
// Chunk order: ic OUTER, k INNER -> for fixed ic the 7 k-gathers hit the same
// ~40KB x-slab; k=0 warms L1, k=1..6 hit L1. Tables preloaded in registers.
// 2-slot smem ring; per slot: A_hi@0, A_lo@16K, B_hi@32K, B_lo@48K (64KB).
// Named barriers: full[s]=1+s (prod arrive, cons sync), empty[s]=3+s (cons arrive, prod sync).
__global__ __launch_bounds__(384, 1) void main_kernel(
    const float* __restrict__ x,
    const float* __restrict__ bias,
    float* __restrict__ out)
{
    extern __shared__ char smem[];
    uint32_t sb = smem_u32(smem);

    int tid = threadIdx.x;
    int l0  = blockIdx.x * NT;
    int oh  = blockIdx.y;
    int b   = blockIdx.z;
    const float* xb = x + (size_t)b * CIN * LEN;

    if (tid < 256) {
        // ================= consumers =================
        int wid  = tid >> 5;
        int lane = tid & 31;
        int ow   = wid >> 2;     // 0..1 -> 64-o subtile
        int lw   = wid & 3;      // 0..3 -> 32-l subtile

        float c[4][4][4];
        #pragma unroll
        for (int ot = 0; ot < 4; ot++)
            #pragma unroll
            for (int nt = 0; nt < 4; nt++)
                #pragma unroll
                for (int r = 0; r < 4; r++) c[ot][nt][r] = 0.f;

        for (int cc = 0; cc < KK * NCHUNK; cc++) {
            int slot = cc & 1;
            BAR_SYNC(1 + slot);                    // wait full
            uint32_t aHI = sb + slot * SLOT_BYTES;
            uint32_t aLO = aHI + 16384;
            uint32_t bHI = aHI + 32768;
            uint32_t bLO = aHI + 49152;

            #pragma unroll
            for (int ks = 0; ks < 4; ks++) {
                uint32_t bh[4][2], bl[4][2];
                #pragma unroll
                for (int np = 0; np < 2; np++) {
                    int row = lw * 32 + np * 16 + ((lane >> 4) << 3) + (lane & 7);
                    uint32_t off = SWZ128((uint32_t)(row * 128 + ks * 32 + ((lane >> 3) & 1) * 16));
                    uint32_t r[4];
                    ldsm4(r, bHI + off);
                    bh[np * 2][0]     = r[0]; bh[np * 2][1]     = r[1];
                    bh[np * 2 + 1][0] = r[2]; bh[np * 2 + 1][1] = r[3];
                    ldsm4(r, bLO + off);
                    bl[np * 2][0]     = r[0]; bl[np * 2][1]     = r[1];
                    bl[np * 2 + 1][0] = r[2]; bl[np * 2 + 1][1] = r[3];
                }
                #pragma unroll
                for (int ot = 0; ot < 4; ot++) {
                    int row = ow * 64 + ot * 16 + (lane & 15);
                    uint32_t off = SWZ128((uint32_t)(row * 128 + ks * 32 + (lane >> 4) * 16));
                    uint32_t ah[4], al[4];
                    ldsm4(ah, aHI + off);
                    ldsm4(al, aLO + off);
                    #pragma unroll
                    for (int nt = 0; nt < 4; nt++) {
                        mma16816(c[ot][nt], ah, bh[nt]);
                        mma16816(c[ot][nt], ah, bl[nt]);
                        mma16816(c[ot][nt], al, bh[nt]);
                    }
                }
            }
            if (cc < KK * NCHUNK - 2) BAR_ARRIVE(3 + slot);   // signal empty
        }

        // ---- epilogue: bias + store ----
        int og0 = oh * 128 + ow * 64;
        #pragma unroll
        for (int ot = 0; ot < 4; ot++) {
            #pragma unroll
            for (int r2 = 0; r2 < 2; r2++) {
                int o = og0 + ot * 16 + (lane >> 2) + r2 * 8;
                float bj = bias[o];
                float* orow = out + ((size_t)(b * COUT + o)) * LEN + l0;
                #pragma unroll
                for (int nt = 0; nt < 4; nt++) {
                    int lc = lw * 32 + nt * 8 + (lane & 3) * 2;
                    *(float2*)(orow + lc) =
                        make_float2(c[ot][nt][r2 * 2] + bj, c[ot][nt][r2 * 2 + 1] + bj);
                }
            }
        }
    } else {
        // ================= producers =================
        int ptid = tid - 256;      // 0..127, one l-row each

        // preload all 7 interpolation tables (depend on (k,l) only, not ic)
        const float* p0r[KK];
        const float* p1r[KK];
        float2 wvr[KK];
        #pragma unroll
        for (int k = 0; k < KK; k++) {
            int tix = (b * 7 + k) * LEN + l0 + ptid;
            int2 ii = g_tidx[tix];
            wvr[k]  = g_tw[tix];
            p0r[k]  = xb + ii.x;
            p1r[k]  = xb + ii.y;
        }

        for (int cc = 0; cc < KK * NCHUNK; cc++) {
            int ic   = cc / KK;    // ic outer, k inner: L1 slab reuse across k
            int k    = cc - ic * KK;
            int slot = cc & 1;
            if (cc >= 2) BAR_SYNC(3 + slot);       // wait empty

            // ---- A tiles (hi+lo, 32KB contiguous) via cp.async ----
            uint32_t aBase = sb + slot * SLOT_BYTES;
            int tb = ((k * NCHUNK + ic) * 2 + oh) * 2;
            const char* srcA = (const char*)(g_wA + (size_t)tb * 8192);
            #pragma unroll
            for (int q = 0; q < 16; q++)
                cp16(aBase + q * 2048 + ptid * 16, srcA + q * 2048 + ptid * 16);
            asm volatile("cp.async.commit_group;" ::: "memory");

            // ---- B tile: gather + interp + hi/lo split -> SW128 smem ----
            float2 wv = wvr[k];
            const float* p0 = p0r[k];
            const float* p1 = p1r[k];
            char* bH = smem + slot * SLOT_BYTES + 32768;
            char* bL = smem + slot * SLOT_BYTES + 49152;

            #pragma unroll
            for (int g = 0; g < 8; g++) {
                uint32_t hp[4], lp[4];
                #pragma unroll
                for (int j = 0; j < 4; j++) {
                    size_t i0 = (size_t)(ic * 64 + g * 8 + j * 2) * LEN;
                    float v0 = wv.x * p0[i0]       + wv.y * p1[i0];
                    float v1 = wv.x * p0[i0 + LEN] + wv.y * p1[i0 + LEN];
                    uint32_t hh = cvt_bf16x2(v0, v1);
                    float e0 = v0 - __uint_as_float(hh << 16);
                    float e1 = v1 - __uint_as_float(hh & 0xFFFF0000u);
                    hp[j] = hh;
                    lp[j] = cvt_bf16x2(e0, e1);
                }
                uint32_t so = SWZ128((uint32_t)(ptid * 128 + g * 16));
                *(uint4*)(bH + so) = make_uint4(hp[0], hp[1], hp[2], hp[3]);
                *(uint4*)(bL + so) = make_uint4(lp[0], lp[1], lp[2], lp[3]);
            }
            asm volatile("cp.async.wait_group 0;" ::: "memory");
            __threadfence_block();
            BAR_ARRIVE(1 + slot);                  // signal full
        }
    }
}

// ---------------- launch ----------------
extern "C" void kernel_launch(void* const* d_in, const int* in_sizes, int n_in,
                              void* d_out, int out_size)
{
    const float* x        = (const float*)d_in[0];
    const float* weight   = (const float*)d_in[1];
    const float* bias     = (const float*)d_in[2];
    const float* offset_w = (const float*)d_in[3];
    const float* offset_b = (const float*)d_in[4];
    float* out = (float*)d_out;

    const int smem_off  = (256 * 136 + 7 * 256 * 8) * 4;   // 196608
    const int smem_main = 2 * SLOT_BYTES;                  // 131072

    cudaFuncSetAttribute(offsets_kernel, cudaFuncAttributeMaxDynamicSharedMemorySize, smem_off);
    cudaFuncSetAttribute(main_kernel,    cudaFuncAttributeMaxDynamicSharedMemorySize, smem_main);

    wprep_kernel<<<(KK * NCHUNK * 2 * 2 * 8192 + 255) / 256, 256>>>(weight);
    offsets_kernel<<<dim3(LEN / TLO, BATCH), 256, smem_off>>>(x, offset_w, offset_b);
    main_kernel<<<dim3(LEN / NT, 2, BATCH), 384, smem_main>>>(x, bias, out);
}

// round 9
// speedup vs baseline: 2.3601x; 2.3601x over previous
#include <cuda_runtime.h>
#include <cuda_fp16.h>
#include <cstdint>

#define CIN   256
#define COUT  256
#define LEN   8192
#define KK    7
#define BATCH 4
#define NT    128    // l-tile of main kernel
#define TLO   128    // l-tile of offsets kernel
#define NCHUNK 4     // i-chunks of 64 per k

// ---------------- device scratch ----------------
__device__ int2   g_tidx[BATCH * KK * LEN];   // (x0c, x1c)
__device__ float2 g_tw[BATCH * KK * LEN];     // (wa, wb)
// weight tiles: t = ((k*4+ic)*2+oh)*2+plane, each [128 o][64 i] fp16, SW128 pre-swizzled
// plane0 = fp16(W) (hi), plane1 = fp16(W - hi) (lo)
__device__ __half g_wA[KK * NCHUNK * 2 * 2 * 8192];

#define SWZ128(x)  ((x) ^ (((x) >> 3) & 0x70))
#define SLOT_BYTES 49152   // A_hi 16K + A_lo 16K + B 16K

// ---------------- PTX helpers (portable, sm_80-era) ----------------
__device__ __forceinline__ uint32_t smem_u32(const void* p) {
    uint32_t a;
    asm("{ .reg .u64 t; cvta.to.shared.u64 t, %1; cvt.u32.u64 %0, t; }" : "=r"(a) : "l"(p));
    return a;
}
__device__ __forceinline__ void cp16(uint32_t dst, const void* src) {
    asm volatile("cp.async.cg.shared.global [%0], [%1], 16;" :: "r"(dst), "l"(src));
}
__device__ __forceinline__ void ldsm4(uint32_t* r, uint32_t addr) {
    asm volatile("ldmatrix.sync.aligned.m8n8.x4.shared.b16 {%0,%1,%2,%3}, [%4];"
        : "=r"(r[0]), "=r"(r[1]), "=r"(r[2]), "=r"(r[3]) : "r"(addr));
}
__device__ __forceinline__ void mma16816(float* c, const uint32_t* a, const uint32_t* b) {
    asm volatile("mma.sync.aligned.m16n8k16.row.col.f32.f16.f16.f32 "
        "{%0,%1,%2,%3}, {%4,%5,%6,%7}, {%8,%9}, {%0,%1,%2,%3};"
        : "+f"(c[0]), "+f"(c[1]), "+f"(c[2]), "+f"(c[3])
        : "r"(a[0]), "r"(a[1]), "r"(a[2]), "r"(a[3]), "r"(b[0]), "r"(b[1]));
}
// pack two f32 -> f16x2 (rn); first src operand -> high half (matches __floats2half2_rn)
__device__ __forceinline__ uint32_t cvt_f16x2(float lo, float hi) {
    uint32_t r;
    asm("cvt.rn.f16x2.f32 %0, %1, %2;" : "=r"(r) : "f"(hi), "f"(lo));
    return r;
}
#define BAR_SYNC(id)   asm volatile("bar.sync %0, %1;"   :: "r"(id), "r"(384) : "memory")
#define BAR_ARRIVE(id) asm volatile("bar.arrive %0, %1;" :: "r"(id), "r"(384) : "memory")

// ---------- kernel 1: weight split (fp16 hi/lo) + pre-swizzle ----------
__global__ void wprep_kernel(const float* __restrict__ w) {
    int e = blockIdx.x * 256 + threadIdx.x;
    if (e >= KK * NCHUNK * 2 * 2 * 8192) return;
    int t  = e >> 13;
    int r  = e & 8191;
    int o  = r >> 6;
    int i  = r & 63;
    int plane = t & 1;
    int oh    = (t >> 1) & 1;
    int ic    = (t >> 2) & 3;
    int k     = t >> 4;
    float v = w[((oh * 128 + o) * CIN + ic * 64 + i) * KK + k];
    __half hi  = __float2half(v);
    __half val = plane ? __float2half(v - __half2float(hi)) : hi;
    uint32_t swz = SWZ128((uint32_t)(o * 128 + i * 2));
    g_wA[t * 8192 + (swz >> 1)] = val;
}

// ---------- kernel 2: offset conv + interpolation tables ----------
__global__ __launch_bounds__(256, 1) void offsets_kernel(
    const float* __restrict__ x,
    const float* __restrict__ ow,
    const float* __restrict__ ob)
{
    extern __shared__ float sm[];
    float* xs  = sm;              // 256 * 136
    float* ows = sm + 256 * 136;  // 7 * 256 * 8

    int tid = threadIdx.x;
    int b   = blockIdx.y;
    int l0  = blockIdx.x * TLO;
    const float* xb = x + (size_t)b * CIN * LEN;

    for (int idx = tid; idx < 256 * 134; idx += 256) {
        int i = idx / 134;
        int c = idx - i * 134;
        int g = l0 - 3 + c;
        xs[i * 136 + c] = (g >= 0 && g < LEN) ? xb[i * LEN + g] : 0.0f;
    }
    for (int e = tid; e < KK * CIN * KK; e += 256) {
        int r  = e / 7;
        int kk = e - r * 7;
        ows[r * 8 + kk] = ow[e];
    }
    __syncthreads();

    int w    = tid >> 5;
    int lane = tid & 31;
    if (w < 7) {
        int k = w;
        float a0 = 0.f, a1 = 0.f, a2 = 0.f, a3 = 0.f;
        const float* xrow0 = xs + 4 * lane;
        const float* wrow  = ows + k * 256 * 8;
        #pragma unroll 4
        for (int i = 0; i < 256; i++) {
            const float4* xr = (const float4*)(xrow0 + i * 136);
            float4 A = xr[0], B4 = xr[1], C4 = xr[2];
            float xw[12] = {A.x, A.y, A.z, A.w, B4.x, B4.y, B4.z, B4.w,
                            C4.x, C4.y, C4.z, C4.w};
            const float4* wr = (const float4*)(wrow + i * 8);
            float4 W0 = wr[0], W1 = wr[1];
            float wv[7] = {W0.x, W0.y, W0.z, W0.w, W1.x, W1.y, W1.z};
            #pragma unroll
            for (int kk = 0; kk < 7; kk++) {
                a0 += wv[kk] * xw[0 + kk];
                a1 += wv[kk] * xw[1 + kk];
                a2 += wv[kk] * xw[2 + kk];
                a3 += wv[kk] * xw[3 + kk];
            }
        }
        float bk = ob[k];
        float accs[4] = {a0, a1, a2, a3};
        #pragma unroll
        for (int d = 0; d < 4; d++) {
            int lg = l0 + 4 * lane + d;
            float loc = (float)(lg + k) + accs[d] + bk;
            int ix0 = (int)floorf(loc);
            int i0c = min(max(ix0, 0), LEN - 1);
            int i1c = min(max(ix0 + 1, 0), LEN - 1);
            int o = (b * 7 + k) * LEN + lg;
            g_tidx[o] = make_int2(i0c, i1c);
            g_tw[o]   = make_float2((float)i1c - loc, loc - (float)i0c);
        }
    }
}

// ---------- kernel 3: warp-specialized GEMM (fp16, W 2-plane) ----------
// 384 threads: warps 0-7 consumers (mma), warps 8-11 producers (A cp.async + B gather).
// Chunk order: k outer, ic inner (R6 proven). 2-slot smem ring; per slot:
// A_hi@0, A_lo@16K, B@32K (48KB). out = (Wh+Wl)*Ih.
// Named barriers: full[s]=1+s (prod arrive, cons sync), empty[s]=3+s (cons arrive, prod sync).
__global__ __launch_bounds__(384, 1) void main_kernel(
    const float* __restrict__ x,
    const float* __restrict__ bias,
    float* __restrict__ out)
{
    extern __shared__ char smem[];
    uint32_t sb = smem_u32(smem);

    int tid = threadIdx.x;
    int l0  = blockIdx.x * NT;
    int oh  = blockIdx.y;
    int b   = blockIdx.z;
    const float* xb = x + (size_t)b * CIN * LEN;

    if (tid < 256) {
        // ================= consumers =================
        int wid  = tid >> 5;
        int lane = tid & 31;
        int ow   = wid >> 2;     // 0..1 -> 64-o subtile
        int lw   = wid & 3;      // 0..3 -> 32-l subtile

        float c[4][4][4];
        #pragma unroll
        for (int ot = 0; ot < 4; ot++)
            #pragma unroll
            for (int nt = 0; nt < 4; nt++)
                #pragma unroll
                for (int r = 0; r < 4; r++) c[ot][nt][r] = 0.f;

        for (int cc = 0; cc < KK * NCHUNK; cc++) {
            int slot = cc & 1;
            BAR_SYNC(1 + slot);                    // wait full
            uint32_t aHI = sb + slot * SLOT_BYTES;
            uint32_t aLO = aHI + 16384;
            uint32_t bB  = aHI + 32768;

            #pragma unroll
            for (int ks = 0; ks < 4; ks++) {
                uint32_t bf[4][2];
                #pragma unroll
                for (int np = 0; np < 2; np++) {
                    // non-trans B load: m0=(ntile 2np, k-lo), m1=(ntile 2np, k-hi),
                    //                   m2=(ntile 2np+1, k-lo), m3=(ntile 2np+1, k-hi)
                    int row = lw * 32 + np * 16 + ((lane >> 4) << 3) + (lane & 7);
                    uint32_t off = SWZ128((uint32_t)(row * 128 + ks * 32 + ((lane >> 3) & 1) * 16));
                    uint32_t r[4];
                    ldsm4(r, bB + off);
                    bf[np * 2][0]     = r[0]; bf[np * 2][1]     = r[1];
                    bf[np * 2 + 1][0] = r[2]; bf[np * 2 + 1][1] = r[3];
                }
                #pragma unroll
                for (int ot = 0; ot < 4; ot++) {
                    int row = ow * 64 + ot * 16 + (lane & 15);
                    uint32_t off = SWZ128((uint32_t)(row * 128 + ks * 32 + (lane >> 4) * 16));
                    uint32_t ah[4], al[4];
                    ldsm4(ah, aHI + off);
                    ldsm4(al, aLO + off);
                    #pragma unroll
                    for (int nt = 0; nt < 4; nt++) {
                        mma16816(c[ot][nt], ah, bf[nt]);
                        mma16816(c[ot][nt], al, bf[nt]);
                    }
                }
            }
            if (cc < KK * NCHUNK - 2) BAR_ARRIVE(3 + slot);   // signal empty
        }

        // ---- epilogue: bias + store ----
        int og0 = oh * 128 + ow * 64;
        #pragma unroll
        for (int ot = 0; ot < 4; ot++) {
            #pragma unroll
            for (int r2 = 0; r2 < 2; r2++) {
                int o = og0 + ot * 16 + (lane >> 2) + r2 * 8;
                float bj = bias[o];
                float* orow = out + ((size_t)(b * COUT + o)) * LEN + l0;
                #pragma unroll
                for (int nt = 0; nt < 4; nt++) {
                    int lc = lw * 32 + nt * 8 + (lane & 3) * 2;
                    *(float2*)(orow + lc) =
                        make_float2(c[ot][nt][r2 * 2] + bj, c[ot][nt][r2 * 2 + 1] + bj);
                }
            }
        }
    } else {
        // ================= producers =================
        int ptid = tid - 256;      // 0..127, one l-row each

        for (int cc = 0; cc < KK * NCHUNK; cc++) {
            int k    = cc >> 2;    // k outer, ic inner (R6 proven order)
            int ic   = cc & 3;
            int slot = cc & 1;
            if (cc >= 2) BAR_SYNC(3 + slot);       // wait empty

            // ---- A tiles (hi+lo, 32KB contiguous) via cp.async ----
            uint32_t aBase = sb + slot * SLOT_BYTES;
            int tb = ((k * NCHUNK + ic) * 2 + oh) * 2;
            const char* srcA = (const char*)(g_wA + (size_t)tb * 8192);
            #pragma unroll
            for (int q = 0; q < 16; q++)
                cp16(aBase + q * 2048 + ptid * 16, srcA + q * 2048 + ptid * 16);
            asm volatile("cp.async.commit_group;" ::: "memory");

            // ---- B tile: gather + interp -> fp16 SW128 smem (single plane) ----
            int tix = (b * 7 + k) * LEN + l0 + ptid;
            int2   ii = g_tidx[tix];
            float2 wv = g_tw[tix];
            const float* p0 = xb + ii.x;
            const float* p1 = xb + ii.y;
            char* bB = smem + slot * SLOT_BYTES + 32768;

            #pragma unroll
            for (int g = 0; g < 8; g++) {
                uint32_t hp[4];
                #pragma unroll
                for (int j = 0; j < 4; j++) {
                    size_t i0 = (size_t)(ic * 64 + g * 8 + j * 2) * LEN;
                    float v0 = wv.x * p0[i0]       + wv.y * p1[i0];
                    float v1 = wv.x * p0[i0 + LEN] + wv.y * p1[i0 + LEN];
                    hp[j] = cvt_f16x2(v0, v1);
                }
                uint32_t so = SWZ128((uint32_t)(ptid * 128 + g * 16));
                *(uint4*)(bB + so) = make_uint4(hp[0], hp[1], hp[2], hp[3]);
            }
            asm volatile("cp.async.wait_group 0;" ::: "memory");
            __threadfence_block();
            BAR_ARRIVE(1 + slot);                  // signal full
        }
    }
}

// ---------------- launch ----------------
extern "C" void kernel_launch(void* const* d_in, const int* in_sizes, int n_in,
                              void* d_out, int out_size)
{
    const float* x        = (const float*)d_in[0];
    const float* weight   = (const float*)d_in[1];
    const float* bias     = (const float*)d_in[2];
    const float* offset_w = (const float*)d_in[3];
    const float* offset_b = (const float*)d_in[4];
    float* out = (float*)d_out;

    const int smem_off  = (256 * 136 + 7 * 256 * 8) * 4;   // 196608
    const int smem_main = 2 * SLOT_BYTES;                  // 98304

    cudaFuncSetAttribute(offsets_kernel, cudaFuncAttributeMaxDynamicSharedMemorySize, smem_off);
    cudaFuncSetAttribute(main_kernel,    cudaFuncAttributeMaxDynamicSharedMemorySize, smem_main);

    wprep_kernel<<<(KK * NCHUNK * 2 * 2 * 8192 + 255) / 256, 256>>>(weight);
    offsets_kernel<<<dim3(LEN / TLO, BATCH), 256, smem_off>>>(x, offset_w, offset_b);
    main_kernel<<<dim3(LEN / NT, 2, BATCH), 384, smem_main>>>(x, bias, out);
}

// round 10
// speedup vs baseline: 2.7431x; 1.1623x over previous
#include <cuda_runtime.h>
#include <cuda_fp16.h>
#include <cstdint>

#define CIN   256
#define COUT  256
#define LEN   8192
#define KK    7
#define BATCH 4
#define NT    128    // l-tile of main kernel
#define TLO   128    // l-tile of offsets kernel
#define NCHUNK 4     // i-chunks of 64 per k

// ---------------- device scratch ----------------
__device__ int2   g_tidx[BATCH * KK * LEN];   // (x0c, x1c)
__device__ float2 g_tw[BATCH * KK * LEN];     // (wa, wb)
// weight tiles: t = (k*4+ic)*2+oh, each [128 o][64 i] fp16, SW128 pre-swizzled
__device__ __half g_wA[KK * NCHUNK * 2 * 8192];

#define SWZ128(x)  ((x) ^ (((x) >> 3) & 0x70))
#define SLOT_BYTES 32768   // A 16K + B 16K
#define NSLOT 3

// ---------------- PTX helpers (portable, sm_80-era) ----------------
__device__ __forceinline__ uint32_t smem_u32(const void* p) {
    uint32_t a;
    asm("{ .reg .u64 t; cvta.to.shared.u64 t, %1; cvt.u32.u64 %0, t; }" : "=r"(a) : "l"(p));
    return a;
}
__device__ __forceinline__ void cp16(uint32_t dst, const void* src) {
    asm volatile("cp.async.cg.shared.global [%0], [%1], 16;" :: "r"(dst), "l"(src));
}
__device__ __forceinline__ void ldsm4(uint32_t* r, uint32_t addr) {
    asm volatile("ldmatrix.sync.aligned.m8n8.x4.shared.b16 {%0,%1,%2,%3}, [%4];"
        : "=r"(r[0]), "=r"(r[1]), "=r"(r[2]), "=r"(r[3]) : "r"(addr));
}
__device__ __forceinline__ void mma16816(float* c, const uint32_t* a, const uint32_t* b) {
    asm volatile("mma.sync.aligned.m16n8k16.row.col.f32.f16.f16.f32 "
        "{%0,%1,%2,%3}, {%4,%5,%6,%7}, {%8,%9}, {%0,%1,%2,%3};"
        : "+f"(c[0]), "+f"(c[1]), "+f"(c[2]), "+f"(c[3])
        : "r"(a[0]), "r"(a[1]), "r"(a[2]), "r"(a[3]), "r"(b[0]), "r"(b[1]));
}
// pack two f32 -> f16x2 (rn); first src operand -> high half
__device__ __forceinline__ uint32_t cvt_f16x2(float lo, float hi) {
    uint32_t r;
    asm("cvt.rn.f16x2.f32 %0, %1, %2;" : "=r"(r) : "f"(hi), "f"(lo));
    return r;
}
#define BAR_SYNC(id)   asm volatile("bar.sync %0, %1;"   :: "r"(id), "r"(384) : "memory")
#define BAR_ARRIVE(id) asm volatile("bar.arrive %0, %1;" :: "r"(id), "r"(384) : "memory")

// ---------- kernel 1: weight fp16 + pre-swizzle (hi plane only) ----------
__global__ void wprep_kernel(const float* __restrict__ w) {
    int e = blockIdx.x * 256 + threadIdx.x;
    if (e >= KK * NCHUNK * 2 * 8192) return;
    int t  = e >> 13;
    int r  = e & 8191;
    int o  = r >> 6;
    int i  = r & 63;
    int oh = t & 1;
    int ic = (t >> 1) & 3;
    int k  = t >> 3;
    float v = w[((oh * 128 + o) * CIN + ic * 64 + i) * KK + k];
    uint32_t swz = SWZ128((uint32_t)(o * 128 + i * 2));
    g_wA[t * 8192 + (swz >> 1)] = __float2half(v);
}

// ---------- kernel 2: offset conv + interpolation tables ----------
__global__ __launch_bounds__(256, 1) void offsets_kernel(
    const float* __restrict__ x,
    const float* __restrict__ ow,
    const float* __restrict__ ob)
{
    extern __shared__ float sm[];
    float* xs  = sm;              // 256 * 136
    float* ows = sm + 256 * 136;  // 7 * 256 * 8

    int tid = threadIdx.x;
    int b   = blockIdx.y;
    int l0  = blockIdx.x * TLO;
    const float* xb = x + (size_t)b * CIN * LEN;

    for (int idx = tid; idx < 256 * 134; idx += 256) {
        int i = idx / 134;
        int c = idx - i * 134;
        int g = l0 - 3 + c;
        xs[i * 136 + c] = (g >= 0 && g < LEN) ? xb[i * LEN + g] : 0.0f;
    }
    for (int e = tid; e < KK * CIN * KK; e += 256) {
        int r  = e / 7;
        int kk = e - r * 7;
        ows[r * 8 + kk] = ow[e];
    }
    __syncthreads();

    int w    = tid >> 5;
    int lane = tid & 31;
    if (w < 7) {
        int k = w;
        float a0 = 0.f, a1 = 0.f, a2 = 0.f, a3 = 0.f;
        const float* xrow0 = xs + 4 * lane;
        const float* wrow  = ows + k * 256 * 8;
        #pragma unroll 4
        for (int i = 0; i < 256; i++) {
            const float4* xr = (const float4*)(xrow0 + i * 136);
            float4 A = xr[0], B4 = xr[1], C4 = xr[2];
            float xw[12] = {A.x, A.y, A.z, A.w, B4.x, B4.y, B4.z, B4.w,
                            C4.x, C4.y, C4.z, C4.w};
            const float4* wr = (const float4*)(wrow + i * 8);
            float4 W0 = wr[0], W1 = wr[1];
            float wv[7] = {W0.x, W0.y, W0.z, W0.w, W1.x, W1.y, W1.z};
            #pragma unroll
            for (int kk = 0; kk < 7; kk++) {
                a0 += wv[kk] * xw[0 + kk];
                a1 += wv[kk] * xw[1 + kk];
                a2 += wv[kk] * xw[2 + kk];
                a3 += wv[kk] * xw[3 + kk];
            }
        }
        float bk = ob[k];
        float accs[4] = {a0, a1, a2, a3};
        #pragma unroll
        for (int d = 0; d < 4; d++) {
            int lg = l0 + 4 * lane + d;
            float loc = (float)(lg + k) + accs[d] + bk;
            int ix0 = (int)floorf(loc);
            int i0c = min(max(ix0, 0), LEN - 1);
            int i1c = min(max(ix0 + 1, 0), LEN - 1);
            int o = (b * 7 + k) * LEN + lg;
            g_tidx[o] = make_int2(i0c, i1c);
            g_tw[o]   = make_float2((float)i1c - loc, loc - (float)i0c);
        }
    }
}

// ---------- kernel 3: warp-specialized GEMM (fp16, single plane) ----------
// 384 threads: warps 0-7 consumers (mma), warps 8-11 producers (A cp.async + B gather).
// Chunk order: k outer, ic inner. 3-slot smem ring; per slot: A@0, B@16K (32KB).
// Named barriers: full[s]=1+s (prod arrive, cons sync), empty[s]=4+s (cons arrive, prod sync).
__global__ __launch_bounds__(384, 1) void main_kernel(
    const float* __restrict__ x,
    const float* __restrict__ bias,
    float* __restrict__ out)
{
    extern __shared__ char smem[];
    uint32_t sb = smem_u32(smem);

    int tid = threadIdx.x;
    int l0  = blockIdx.x * NT;
    int oh  = blockIdx.y;
    int b   = blockIdx.z;
    const float* xb = x + (size_t)b * CIN * LEN;

    if (tid < 256) {
        // ================= consumers =================
        int wid  = tid >> 5;
        int lane = tid & 31;
        int ow   = wid >> 2;     // 0..1 -> 64-o subtile
        int lw   = wid & 3;      // 0..3 -> 32-l subtile

        float c[4][4][4];
        #pragma unroll
        for (int ot = 0; ot < 4; ot++)
            #pragma unroll
            for (int nt = 0; nt < 4; nt++)
                #pragma unroll
                for (int r = 0; r < 4; r++) c[ot][nt][r] = 0.f;

        int slot = 0;
        for (int cc = 0; cc < KK * NCHUNK; cc++) {
            BAR_SYNC(1 + slot);                    // wait full
            uint32_t aB = sb + slot * SLOT_BYTES;
            uint32_t bB = aB + 16384;

            #pragma unroll
            for (int ks = 0; ks < 4; ks++) {
                uint32_t bf[4][2];
                #pragma unroll
                for (int np = 0; np < 2; np++) {
                    // non-trans B load: m0=(ntile 2np, k-lo), m1=(ntile 2np, k-hi),
                    //                   m2=(ntile 2np+1, k-lo), m3=(ntile 2np+1, k-hi)
                    int row = lw * 32 + np * 16 + ((lane >> 4) << 3) + (lane & 7);
                    uint32_t off = SWZ128((uint32_t)(row * 128 + ks * 32 + ((lane >> 3) & 1) * 16));
                    uint32_t r[4];
                    ldsm4(r, bB + off);
                    bf[np * 2][0]     = r[0]; bf[np * 2][1]     = r[1];
                    bf[np * 2 + 1][0] = r[2]; bf[np * 2 + 1][1] = r[3];
                }
                #pragma unroll
                for (int ot = 0; ot < 4; ot++) {
                    int row = ow * 64 + ot * 16 + (lane & 15);
                    uint32_t off = SWZ128((uint32_t)(row * 128 + ks * 32 + (lane >> 4) * 16));
                    uint32_t ah[4];
                    ldsm4(ah, aB + off);
                    #pragma unroll
                    for (int nt = 0; nt < 4; nt++)
                        mma16816(c[ot][nt], ah, bf[nt]);
                }
            }
            if (cc < KK * NCHUNK - NSLOT) BAR_ARRIVE(4 + slot);   // signal empty
            slot = (slot == NSLOT - 1) ? 0 : slot + 1;
        }

        // ---- epilogue: bias + store ----
        int og0 = oh * 128 + ow * 64;
        #pragma unroll
        for (int ot = 0; ot < 4; ot++) {
            #pragma unroll
            for (int r2 = 0; r2 < 2; r2++) {
                int o = og0 + ot * 16 + (lane >> 2) + r2 * 8;
                float bj = bias[o];
                float* orow = out + ((size_t)(b * COUT + o)) * LEN + l0;
                #pragma unroll
                for (int nt = 0; nt < 4; nt++) {
                    int lc = lw * 32 + nt * 8 + (lane & 3) * 2;
                    *(float2*)(orow + lc) =
                        make_float2(c[ot][nt][r2 * 2] + bj, c[ot][nt][r2 * 2 + 1] + bj);
                }
            }
        }
    } else {
        // ================= producers =================
        int ptid = tid - 256;      // 0..127, one l-row each

        int slot = 0;
        for (int cc = 0; cc < KK * NCHUNK; cc++) {
            int k  = cc >> 2;      // k outer, ic inner
            int ic = cc & 3;
            if (cc >= NSLOT) BAR_SYNC(4 + slot);   // wait empty

            // ---- A tile (16KB) via cp.async ----
            uint32_t aBase = sb + slot * SLOT_BYTES;
            int tb = (k * NCHUNK + ic) * 2 + oh;
            const char* srcA = (const char*)(g_wA + (size_t)tb * 8192);
            #pragma unroll
            for (int q = 0; q < 8; q++)
                cp16(aBase + q * 2048 + ptid * 16, srcA + q * 2048 + ptid * 16);
            asm volatile("cp.async.commit_group;" ::: "memory");

            // ---- B tile: gather + interp -> fp16 SW128 smem ----
            int tix = (b * 7 + k) * LEN + l0 + ptid;
            int2   ii = g_tidx[tix];
            float2 wv = g_tw[tix];
            const float* p0 = xb + ii.x;
            const float* p1 = xb + ii.y;
            char* bB = smem + slot * SLOT_BYTES + 16384;

            #pragma unroll
            for (int g = 0; g < 8; g++) {
                uint32_t hp[4];
                #pragma unroll
                for (int j = 0; j < 4; j++) {
                    size_t i0 = (size_t)(ic * 64 + g * 8 + j * 2) * LEN;
                    float v0 = wv.x * p0[i0]       + wv.y * p1[i0];
                    float v1 = wv.x * p0[i0 + LEN] + wv.y * p1[i0 + LEN];
                    hp[j] = cvt_f16x2(v0, v1);
                }
                uint32_t so = SWZ128((uint32_t)(ptid * 128 + g * 16));
                *(uint4*)(bB + so) = make_uint4(hp[0], hp[1], hp[2], hp[3]);
            }
            asm volatile("cp.async.wait_group 0;" ::: "memory");
            __threadfence_block();
            BAR_ARRIVE(1 + slot);                  // signal full
            slot = (slot == NSLOT - 1) ? 0 : slot + 1;
        }
    }
}

// ---------------- launch ----------------
extern "C" void kernel_launch(void* const* d_in, const int* in_sizes, int n_in,
                              void* d_out, int out_size)
{
    const float* x        = (const float*)d_in[0];
    const float* weight   = (const float*)d_in[1];
    const float* bias     = (const float*)d_in[2];
    const float* offset_w = (const float*)d_in[3];
    const float* offset_b = (const float*)d_in[4];
    float* out = (float*)d_out;

    const int smem_off  = (256 * 136 + 7 * 256 * 8) * 4;   // 196608
    const int smem_main = NSLOT * SLOT_BYTES;              // 98304

    cudaFuncSetAttribute(offsets_kernel, cudaFuncAttributeMaxDynamicSharedMemorySize, smem_off);
    cudaFuncSetAttribute(main_kernel,    cudaFuncAttributeMaxDynamicSharedMemorySize, smem_main);

    wprep_kernel<<<(KK * NCHUNK * 2 * 8192 + 255) / 256, 256>>>(weight);
    offsets_kernel<<<dim3(LEN / TLO, BATCH), 256, smem_off>>>(x, offset_w, offset_b);
    main_kernel<<<dim3(LEN / NT, 2, BATCH), 384, smem_main>>>(x, bias, out);
}